// round 14
// baseline (speedup 1.0000x reference)
#include <cuda_runtime.h>
#include <cuda_bf16.h>
#include <cstdint>

// NT-Xent: B=4096, D=256, T=0.1
#define N2   8192
#define BH   4096
#define D    256
#define INVT 10.0f

// Scratch (device globals — no allocation allowed)
__device__ __align__(256) __nv_bfloat16 g_pnh[N2 * D];   // normalized rows, bf16 (4 MB)
__device__ __align__(256) float         g_pnf[N2 * D];   // normalized rows, fp32 (8 MB)
__device__ float g_pos[N2];
__device__ float g_part[8][N2];                          // per-(colsplit,warpN) row partials

// ---------------------------------------------------------------------------
// Kernel 1: row-normalize (concat of z_i, z_j) -> fp32 + bf16 copies
// one block (256 threads) per row
// ---------------------------------------------------------------------------
__global__ void prep_kernel(const float* __restrict__ zi, const float* __restrict__ zj) {
    int row = blockIdx.x;
    int t   = threadIdx.x;
    const float* src = (row < BH) ? (zi + (size_t)row * D) : (zj + (size_t)(row - BH) * D);
    float v  = src[t];
    float ss = v * v;
    #pragma unroll
    for (int o = 16; o; o >>= 1) ss += __shfl_xor_sync(0xffffffffu, ss, o);

    __shared__ float wsum[8];
    __shared__ float inv_s;
    int wid = t >> 5, lane = t & 31;
    if (lane == 0) wsum[wid] = ss;
    __syncthreads();
    if (t == 0) {
        float tot = 0.f;
        #pragma unroll
        for (int i = 0; i < 8; ++i) tot += wsum[i];
        inv_s = 1.0f / fmaxf(sqrtf(tot), 1e-8f);
    }
    __syncthreads();
    float o = v * inv_s;
    g_pnf[(size_t)row * D + t] = o;
    g_pnh[(size_t)row * D + t] = __float2bfloat16(o);
}

// ---------------------------------------------------------------------------
// Kernel 2: exact fp32 positive-pair similarity. One warp per row.
// ---------------------------------------------------------------------------
__global__ void pos_kernel() {
    int gwarp = (blockIdx.x * blockDim.x + threadIdx.x) >> 5;
    int lane  = threadIdx.x & 31;
    int i = gwarp;
    int j = (i + BH) & (N2 - 1);
    const float* a = g_pnf + (size_t)i * D;
    const float* b = g_pnf + (size_t)j * D;
    float s = 0.f;
    #pragma unroll
    for (int k = 0; k < D; k += 32) s = fmaf(a[k + lane], b[k + lane], s);
    #pragma unroll
    for (int o = 16; o; o >>= 1) s += __shfl_xor_sync(0xffffffffu, s, o);
    if (lane == 0) g_pos[i] = s * INVT;
}

// ---------------------------------------------------------------------------
// Kernel 3: fused GEMM (pn @ pn^T) + diag-masked exp-sum per row.
// CTA tile 128 rows x 128 cols, K=256 fully resident. 8 warps: 4(M) x 2(N),
// warp tile 32x64, mma.sync.m16n8k16 bf16 -> fp32.
// grid = (64 row tiles, 4 column splits); deterministic partial writes.
// ---------------------------------------------------------------------------
#define LDSU 132   // u32 per SMEM row: 128 data + 4 pad (528 B, conflict-free)

__device__ __forceinline__ void mma16816(float c[4], const uint32_t a[4],
                                         uint32_t b0, uint32_t b1) {
    asm volatile(
        "mma.sync.aligned.m16n8k16.row.col.f32.bf16.bf16.f32 "
        "{%0,%1,%2,%3}, {%4,%5,%6,%7}, {%8,%9}, {%0,%1,%2,%3};\n"
        : "+f"(c[0]), "+f"(c[1]), "+f"(c[2]), "+f"(c[3])
        : "r"(a[0]), "r"(a[1]), "r"(a[2]), "r"(a[3]), "r"(b0), "r"(b1));
}

__global__ void __launch_bounds__(256, 1) main_kernel() {
    extern __shared__ uint32_t sm[];
    uint32_t* As = sm;                 // 128 x 132 u32
    uint32_t* Bs = sm + 128 * LDSU;    // 128 x 132 u32

    int tid  = threadIdx.x;
    int lane = tid & 31;
    int warp = tid >> 5;
    int warpM = warp & 3;              // 0..3  (rows)
    int warpN = warp >> 2;             // 0..1  (cols)
    int quad  = lane & 3;
    int lrow  = lane >> 2;
    int rowBase = blockIdx.x * 128;

    // ---- load A tile (128 x 256 bf16) ----
    {
        const uint4* src = (const uint4*)g_pnh;
        #pragma unroll
        for (int it = 0; it < 16; ++it) {
            int idx = tid + it * 256;          // 0..4095
            int row = idx >> 5, kv = idx & 31; // kv: uint4 (8 bf16) within row
            uint4 v = src[(size_t)(rowBase + row) * (D / 8) + kv];
            *(uint4*)&As[row * LDSU + kv * 4] = v;
        }
    }

    float acc[4] = {0.f, 0.f, 0.f, 0.f};

    const uint32_t* A0 = &As[(warpM * 32 + lrow) * LDSU];
    const uint32_t* B0 = &Bs[(warpN * 64 + lrow) * LDSU];

    for (int ct = 0; ct < 16; ++ct) {
        int colBase = blockIdx.y * 2048 + ct * 128;

        __syncthreads();   // prior consumers of Bs done (also orders A stores on ct=0)
        {
            const uint4* src = (const uint4*)g_pnh;
            #pragma unroll
            for (int it = 0; it < 16; ++it) {
                int idx = tid + it * 256;
                int row = idx >> 5, kv = idx & 31;
                uint4 v = src[(size_t)(colBase + row) * (D / 8) + kv];
                *(uint4*)&Bs[row * LDSU + kv * 4] = v;
            }
        }
        __syncthreads();

        float c[2][8][4];
        #pragma unroll
        for (int mi = 0; mi < 2; ++mi)
            #pragma unroll
            for (int ni = 0; ni < 8; ++ni)
                #pragma unroll
                for (int q = 0; q < 4; ++q) c[mi][ni][q] = 0.f;

        #pragma unroll
        for (int kc = 0; kc < 16; ++kc) {
            int ku = kc * 8 + quad;            // u32 index into a 128-u32 row
            uint32_t a[2][4];
            #pragma unroll
            for (int mi = 0; mi < 2; ++mi) {
                const uint32_t* p = A0 + mi * 16 * LDSU;
                a[mi][0] = p[ku];
                a[mi][1] = p[8 * LDSU + ku];
                a[mi][2] = p[ku + 4];
                a[mi][3] = p[8 * LDSU + ku + 4];
            }
            #pragma unroll
            for (int ni = 0; ni < 8; ++ni) {
                const uint32_t* p = B0 + ni * 8 * LDSU;
                uint32_t b0 = p[ku];
                uint32_t b1 = p[ku + 4];
                mma16816(c[0][ni], a[0], b0, b1);
                mma16816(c[1][ni], a[1], b0, b1);
            }
        }

        // ---- epilogue: exp + diag mask, accumulate per-row ----
        #pragma unroll
        for (int mi = 0; mi < 2; ++mi) {
            int gr0 = rowBase + warpM * 32 + mi * 16 + lrow;
            int gr1 = gr0 + 8;
            #pragma unroll
            for (int ni = 0; ni < 8; ++ni) {
                int gc0 = colBase + warpN * 64 + ni * 8 + quad * 2;
                int gc1 = gc0 + 1;
                float e0 = (gr0 == gc0) ? 0.f : __expf(INVT * c[mi][ni][0]);
                float e1 = (gr0 == gc1) ? 0.f : __expf(INVT * c[mi][ni][1]);
                float e2 = (gr1 == gc0) ? 0.f : __expf(INVT * c[mi][ni][2]);
                float e3 = (gr1 == gc1) ? 0.f : __expf(INVT * c[mi][ni][3]);
                acc[mi * 2 + 0] += e0 + e1;
                acc[mi * 2 + 1] += e2 + e3;
            }
        }
    }

    // reduce across the 4 lanes of each quad (same row, different cols)
    #pragma unroll
    for (int q = 0; q < 4; ++q) {
        acc[q] += __shfl_xor_sync(0xffffffffu, acc[q], 1);
        acc[q] += __shfl_xor_sync(0xffffffffu, acc[q], 2);
    }
    if (quad == 0) {
        int slot = blockIdx.y * 2 + warpN;   // 0..7, unique writer per row
        int r0 = rowBase + warpM * 32 + lrow;
        g_part[slot][r0]      = acc[0];
        g_part[slot][r0 + 8]  = acc[1];
        g_part[slot][r0 + 16] = acc[2];
        g_part[slot][r0 + 24] = acc[3];
    }
}

// ---------------------------------------------------------------------------
// Kernel 4: loss = mean over rows of log(sum partials) - pos
// ---------------------------------------------------------------------------
__global__ void loss_kernel(float* __restrict__ out) {
    __shared__ float red[1024];
    int t = threadIdx.x;
    float s = 0.f;
    for (int r = t; r < N2; r += 1024) {
        float rs = 0.f;
        #pragma unroll
        for (int p = 0; p < 8; ++p) rs += g_part[p][r];
        s += logf(rs) - g_pos[r];
    }
    red[t] = s;
    __syncthreads();
    for (int o = 512; o; o >>= 1) {
        if (t < o) red[t] += red[t + o];
        __syncthreads();
    }
    if (t == 0) out[0] = red[0] / (float)N2;
}

// ---------------------------------------------------------------------------
extern "C" void kernel_launch(void* const* d_in, const int* in_sizes, int n_in,
                              void* d_out, int out_size) {
    const float* zi = (const float*)d_in[0];
    const float* zj = (const float*)d_in[1];
    float* out = (float*)d_out;

    const int SMEM_BYTES = 2 * 128 * LDSU * 4;  // 135168
    cudaFuncSetAttribute(main_kernel, cudaFuncAttributeMaxDynamicSharedMemorySize,
                         SMEM_BYTES);

    prep_kernel<<<N2, 256>>>(zi, zj);
    pos_kernel<<<N2 / 8, 256>>>();
    main_kernel<<<dim3(64, 4), 256, SMEM_BYTES>>>();
    loss_kernel<<<1, 1024>>>(out);
}

// round 15
// speedup vs baseline: 1.0015x; 1.0015x over previous
#include <cuda_runtime.h>
#include <cuda_bf16.h>
#include <cstdint>

// NT-Xent: B=4096, D=256, T=0.1
#define N2   8192
#define BH   4096
#define D    256
#define INVT 10.0f

// Scratch (device globals — no allocation allowed)
__device__ __align__(256) __nv_bfloat16 g_pnh[N2 * D];   // normalized rows, bf16 (4 MB)
__device__ __align__(256) float         g_pnf[N2 * D];   // normalized rows, fp32 (8 MB)
__device__ float g_pos[N2];
__device__ float g_part[8][N2];                          // per-(colsplit,warpN) row partials

// ---------------------------------------------------------------------------
// Kernel 1: row-normalize (concat of z_i, z_j) -> fp32 + bf16 copies
// one block (256 threads) per row
// ---------------------------------------------------------------------------
__global__ void prep_kernel(const float* __restrict__ zi, const float* __restrict__ zj) {
    int row = blockIdx.x;
    int t   = threadIdx.x;
    const float* src = (row < BH) ? (zi + (size_t)row * D) : (zj + (size_t)(row - BH) * D);
    float v  = src[t];
    float ss = v * v;
    #pragma unroll
    for (int o = 16; o; o >>= 1) ss += __shfl_xor_sync(0xffffffffu, ss, o);

    __shared__ float wsum[8];
    __shared__ float inv_s;
    int wid = t >> 5, lane = t & 31;
    if (lane == 0) wsum[wid] = ss;
    __syncthreads();
    if (t == 0) {
        float tot = 0.f;
        #pragma unroll
        for (int i = 0; i < 8; ++i) tot += wsum[i];
        inv_s = 1.0f / fmaxf(sqrtf(tot), 1e-8f);
    }
    __syncthreads();
    float o = v * inv_s;
    g_pnf[(size_t)row * D + t] = o;
    g_pnh[(size_t)row * D + t] = __float2bfloat16(o);
}

// ---------------------------------------------------------------------------
// Kernel 2: exact fp32 positive-pair similarity. One warp per row.
// ---------------------------------------------------------------------------
__global__ void pos_kernel() {
    int gwarp = (blockIdx.x * blockDim.x + threadIdx.x) >> 5;
    int lane  = threadIdx.x & 31;
    int i = gwarp;
    int j = (i + BH) & (N2 - 1);
    const float* a = g_pnf + (size_t)i * D;
    const float* b = g_pnf + (size_t)j * D;
    float s = 0.f;
    #pragma unroll
    for (int k = 0; k < D; k += 32) s = fmaf(a[k + lane], b[k + lane], s);
    #pragma unroll
    for (int o = 16; o; o >>= 1) s += __shfl_xor_sync(0xffffffffu, s, o);
    if (lane == 0) g_pos[i] = s * INVT;
}

// ---------------------------------------------------------------------------
// Kernel 3: fused GEMM (pn @ pn^T) + diag-masked exp-sum per row.
// CTA tile 128 rows x 128 cols, K=256 fully resident. 8 warps: 4(M) x 2(N),
// warp tile 32x64, mma.sync.m16n8k16 bf16 -> fp32.
// grid = (64 row tiles, 4 column splits); deterministic partial writes.
// ---------------------------------------------------------------------------
#define LDSU 132   // u32 per SMEM row: 128 data + 4 pad (528 B, conflict-free)

__device__ __forceinline__ void mma16816(float c[4], const uint32_t a[4],
                                         uint32_t b0, uint32_t b1) {
    asm volatile(
        "mma.sync.aligned.m16n8k16.row.col.f32.bf16.bf16.f32 "
        "{%0,%1,%2,%3}, {%4,%5,%6,%7}, {%8,%9}, {%0,%1,%2,%3};\n"
        : "+f"(c[0]), "+f"(c[1]), "+f"(c[2]), "+f"(c[3])
        : "r"(a[0]), "r"(a[1]), "r"(a[2]), "r"(a[3]), "r"(b0), "r"(b1));
}

__global__ void __launch_bounds__(256, 1) main_kernel() {
    extern __shared__ uint32_t sm[];
    uint32_t* As = sm;                 // 128 x 132 u32
    uint32_t* Bs = sm + 128 * LDSU;    // 128 x 132 u32

    int tid  = threadIdx.x;
    int lane = tid & 31;
    int warp = tid >> 5;
    int warpM = warp & 3;              // 0..3  (rows)
    int warpN = warp >> 2;             // 0..1  (cols)
    int quad  = lane & 3;
    int lrow  = lane >> 2;
    int rowBase = blockIdx.x * 128;

    // ---- load A tile (128 x 256 bf16) ----
    {
        const uint4* src = (const uint4*)g_pnh;
        #pragma unroll
        for (int it = 0; it < 16; ++it) {
            int idx = tid + it * 256;          // 0..4095
            int row = idx >> 5, kv = idx & 31; // kv: uint4 (8 bf16) within row
            uint4 v = src[(size_t)(rowBase + row) * (D / 8) + kv];
            *(uint4*)&As[row * LDSU + kv * 4] = v;
        }
    }

    float acc[4] = {0.f, 0.f, 0.f, 0.f};

    const uint32_t* A0 = &As[(warpM * 32 + lrow) * LDSU];
    const uint32_t* B0 = &Bs[(warpN * 64 + lrow) * LDSU];

    for (int ct = 0; ct < 16; ++ct) {
        int colBase = blockIdx.y * 2048 + ct * 128;

        __syncthreads();   // prior consumers of Bs done (also orders A stores on ct=0)
        {
            const uint4* src = (const uint4*)g_pnh;
            #pragma unroll
            for (int it = 0; it < 16; ++it) {
                int idx = tid + it * 256;
                int row = idx >> 5, kv = idx & 31;
                uint4 v = src[(size_t)(colBase + row) * (D / 8) + kv];
                *(uint4*)&Bs[row * LDSU + kv * 4] = v;
            }
        }
        __syncthreads();

        float c[2][8][4];
        #pragma unroll
        for (int mi = 0; mi < 2; ++mi)
            #pragma unroll
            for (int ni = 0; ni < 8; ++ni)
                #pragma unroll
                for (int q = 0; q < 4; ++q) c[mi][ni][q] = 0.f;

        #pragma unroll
        for (int kc = 0; kc < 16; ++kc) {
            int ku = kc * 8 + quad;            // u32 index into a 128-u32 row
            uint32_t a[2][4];
            #pragma unroll
            for (int mi = 0; mi < 2; ++mi) {
                const uint32_t* p = A0 + mi * 16 * LDSU;
                a[mi][0] = p[ku];
                a[mi][1] = p[8 * LDSU + ku];
                a[mi][2] = p[ku + 4];
                a[mi][3] = p[8 * LDSU + ku + 4];
            }
            #pragma unroll
            for (int ni = 0; ni < 8; ++ni) {
                const uint32_t* p = B0 + ni * 8 * LDSU;
                uint32_t b0 = p[ku];
                uint32_t b1 = p[ku + 4];
                mma16816(c[0][ni], a[0], b0, b1);
                mma16816(c[1][ni], a[1], b0, b1);
            }
        }

        // ---- epilogue: exp + diag mask, accumulate per-row ----
        #pragma unroll
        for (int mi = 0; mi < 2; ++mi) {
            int gr0 = rowBase + warpM * 32 + mi * 16 + lrow;
            int gr1 = gr0 + 8;
            #pragma unroll
            for (int ni = 0; ni < 8; ++ni) {
                int gc0 = colBase + warpN * 64 + ni * 8 + quad * 2;
                int gc1 = gc0 + 1;
                float e0 = (gr0 == gc0) ? 0.f : __expf(INVT * c[mi][ni][0]);
                float e1 = (gr0 == gc1) ? 0.f : __expf(INVT * c[mi][ni][1]);
                float e2 = (gr1 == gc0) ? 0.f : __expf(INVT * c[mi][ni][2]);
                float e3 = (gr1 == gc1) ? 0.f : __expf(INVT * c[mi][ni][3]);
                acc[mi * 2 + 0] += e0 + e1;
                acc[mi * 2 + 1] += e2 + e3;
            }
        }
    }

    // reduce across the 4 lanes of each quad (same row, different cols)
    #pragma unroll
    for (int q = 0; q < 4; ++q) {
        acc[q] += __shfl_xor_sync(0xffffffffu, acc[q], 1);
        acc[q] += __shfl_xor_sync(0xffffffffu, acc[q], 2);
    }
    if (quad == 0) {
        int slot = blockIdx.y * 2 + warpN;   // 0..7, unique writer per row
        int r0 = rowBase + warpM * 32 + lrow;
        g_part[slot][r0]      = acc[0];
        g_part[slot][r0 + 8]  = acc[1];
        g_part[slot][r0 + 16] = acc[2];
        g_part[slot][r0 + 24] = acc[3];
    }
}

// ---------------------------------------------------------------------------
// Kernel 4: loss = mean over rows of log(sum partials) - pos
// ---------------------------------------------------------------------------
__global__ void loss_kernel(float* __restrict__ out) {
    __shared__ float red[1024];
    int t = threadIdx.x;
    float s = 0.f;
    for (int r = t; r < N2; r += 1024) {
        float rs = 0.f;
        #pragma unroll
        for (int p = 0; p < 8; ++p) rs += g_part[p][r];
        s += logf(rs) - g_pos[r];
    }
    red[t] = s;
    __syncthreads();
    for (int o = 512; o; o >>= 1) {
        if (t < o) red[t] += red[t + o];
        __syncthreads();
    }
    if (t == 0) out[0] = red[0] / (float)N2;
}

// ---------------------------------------------------------------------------
extern "C" void kernel_launch(void* const* d_in, const int* in_sizes, int n_in,
                              void* d_out, int out_size) {
    const float* zi = (const float*)d_in[0];
    const float* zj = (const float*)d_in[1];
    float* out = (float*)d_out;

    const int SMEM_BYTES = 2 * 128 * LDSU * 4;  // 135168
    cudaFuncSetAttribute(main_kernel, cudaFuncAttributeMaxDynamicSharedMemorySize,
                         SMEM_BYTES);

    prep_kernel<<<N2, 256>>>(zi, zj);
    pos_kernel<<<N2 / 8, 256>>>();
    main_kernel<<<dim3(64, 4), 256, SMEM_BYTES>>>();
    loss_kernel<<<1, 1024>>>(out);
}

// round 16
// speedup vs baseline: 1.0028x; 1.0013x over previous
#include <cuda_runtime.h>
#include <cuda_bf16.h>
#include <cstdint>

// NT-Xent: B=4096, D=256, T=0.1
#define N2   8192
#define BH   4096
#define D    256
#define INVT 10.0f

// Scratch (device globals — no allocation allowed)
__device__ __align__(256) __nv_bfloat16 g_pnh[N2 * D];   // normalized rows, bf16 (4 MB)
__device__ __align__(256) float         g_pnf[N2 * D];   // normalized rows, fp32 (8 MB)
__device__ float g_pos[N2];
__device__ float g_part[8][N2];                          // per-(colsplit,warpN) row partials

// ---------------------------------------------------------------------------
// Kernel 1: row-normalize (concat of z_i, z_j) -> fp32 + bf16 copies
// one block (256 threads) per row
// ---------------------------------------------------------------------------
__global__ void prep_kernel(const float* __restrict__ zi, const float* __restrict__ zj) {
    int row = blockIdx.x;
    int t   = threadIdx.x;
    const float* src = (row < BH) ? (zi + (size_t)row * D) : (zj + (size_t)(row - BH) * D);
    float v  = src[t];
    float ss = v * v;
    #pragma unroll
    for (int o = 16; o; o >>= 1) ss += __shfl_xor_sync(0xffffffffu, ss, o);

    __shared__ float wsum[8];
    __shared__ float inv_s;
    int wid = t >> 5, lane = t & 31;
    if (lane == 0) wsum[wid] = ss;
    __syncthreads();
    if (t == 0) {
        float tot = 0.f;
        #pragma unroll
        for (int i = 0; i < 8; ++i) tot += wsum[i];
        inv_s = 1.0f / fmaxf(sqrtf(tot), 1e-8f);
    }
    __syncthreads();
    float o = v * inv_s;
    g_pnf[(size_t)row * D + t] = o;
    g_pnh[(size_t)row * D + t] = __float2bfloat16(o);
}

// ---------------------------------------------------------------------------
// Kernel 2: exact fp32 positive-pair similarity. One warp per row.
// ---------------------------------------------------------------------------
__global__ void pos_kernel() {
    int gwarp = (blockIdx.x * blockDim.x + threadIdx.x) >> 5;
    int lane  = threadIdx.x & 31;
    int i = gwarp;
    int j = (i + BH) & (N2 - 1);
    const float* a = g_pnf + (size_t)i * D;
    const float* b = g_pnf + (size_t)j * D;
    float s = 0.f;
    #pragma unroll
    for (int k = 0; k < D; k += 32) s = fmaf(a[k + lane], b[k + lane], s);
    #pragma unroll
    for (int o = 16; o; o >>= 1) s += __shfl_xor_sync(0xffffffffu, s, o);
    if (lane == 0) g_pos[i] = s * INVT;
}

// ---------------------------------------------------------------------------
// Kernel 3: fused GEMM (pn @ pn^T) + diag-masked exp-sum per row.
// CTA tile 128 rows x 128 cols, K=256 fully resident. 8 warps: 4(M) x 2(N),
// warp tile 32x64, mma.sync.m16n8k16 bf16 -> fp32.
// grid = (64 row tiles, 4 column splits); deterministic partial writes.
// ---------------------------------------------------------------------------
#define LDSU 132   // u32 per SMEM row: 128 data + 4 pad (528 B, conflict-free)

__device__ __forceinline__ void mma16816(float c[4], const uint32_t a[4],
                                         uint32_t b0, uint32_t b1) {
    asm volatile(
        "mma.sync.aligned.m16n8k16.row.col.f32.bf16.bf16.f32 "
        "{%0,%1,%2,%3}, {%4,%5,%6,%7}, {%8,%9}, {%0,%1,%2,%3};\n"
        : "+f"(c[0]), "+f"(c[1]), "+f"(c[2]), "+f"(c[3])
        : "r"(a[0]), "r"(a[1]), "r"(a[2]), "r"(a[3]), "r"(b0), "r"(b1));
}

__global__ void __launch_bounds__(256, 1) main_kernel() {
    extern __shared__ uint32_t sm[];
    uint32_t* As = sm;                 // 128 x 132 u32
    uint32_t* Bs = sm + 128 * LDSU;    // 128 x 132 u32

    int tid  = threadIdx.x;
    int lane = tid & 31;
    int warp = tid >> 5;
    int warpM = warp & 3;              // 0..3  (rows)
    int warpN = warp >> 2;             // 0..1  (cols)
    int quad  = lane & 3;
    int lrow  = lane >> 2;
    int rowBase = blockIdx.x * 128;

    // ---- load A tile (128 x 256 bf16) ----
    {
        const uint4* src = (const uint4*)g_pnh;
        #pragma unroll
        for (int it = 0; it < 16; ++it) {
            int idx = tid + it * 256;          // 0..4095
            int row = idx >> 5, kv = idx & 31; // kv: uint4 (8 bf16) within row
            uint4 v = src[(size_t)(rowBase + row) * (D / 8) + kv];
            *(uint4*)&As[row * LDSU + kv * 4] = v;
        }
    }

    float acc[4] = {0.f, 0.f, 0.f, 0.f};

    const uint32_t* A0 = &As[(warpM * 32 + lrow) * LDSU];
    const uint32_t* B0 = &Bs[(warpN * 64 + lrow) * LDSU];

    for (int ct = 0; ct < 16; ++ct) {
        int colBase = blockIdx.y * 2048 + ct * 128;

        __syncthreads();   // prior consumers of Bs done (also orders A stores on ct=0)
        {
            const uint4* src = (const uint4*)g_pnh;
            #pragma unroll
            for (int it = 0; it < 16; ++it) {
                int idx = tid + it * 256;
                int row = idx >> 5, kv = idx & 31;
                uint4 v = src[(size_t)(colBase + row) * (D / 8) + kv];
                *(uint4*)&Bs[row * LDSU + kv * 4] = v;
            }
        }
        __syncthreads();

        float c[2][8][4];
        #pragma unroll
        for (int mi = 0; mi < 2; ++mi)
            #pragma unroll
            for (int ni = 0; ni < 8; ++ni)
                #pragma unroll
                for (int q = 0; q < 4; ++q) c[mi][ni][q] = 0.f;

        #pragma unroll
        for (int kc = 0; kc < 16; ++kc) {
            int ku = kc * 8 + quad;            // u32 index into a 128-u32 row
            uint32_t a[2][4];
            #pragma unroll
            for (int mi = 0; mi < 2; ++mi) {
                const uint32_t* p = A0 + mi * 16 * LDSU;
                a[mi][0] = p[ku];
                a[mi][1] = p[8 * LDSU + ku];
                a[mi][2] = p[ku + 4];
                a[mi][3] = p[8 * LDSU + ku + 4];
            }
            #pragma unroll
            for (int ni = 0; ni < 8; ++ni) {
                const uint32_t* p = B0 + ni * 8 * LDSU;
                uint32_t b0 = p[ku];
                uint32_t b1 = p[ku + 4];
                mma16816(c[0][ni], a[0], b0, b1);
                mma16816(c[1][ni], a[1], b0, b1);
            }
        }

        // ---- epilogue: exp + diag mask, accumulate per-row ----
        #pragma unroll
        for (int mi = 0; mi < 2; ++mi) {
            int gr0 = rowBase + warpM * 32 + mi * 16 + lrow;
            int gr1 = gr0 + 8;
            #pragma unroll
            for (int ni = 0; ni < 8; ++ni) {
                int gc0 = colBase + warpN * 64 + ni * 8 + quad * 2;
                int gc1 = gc0 + 1;
                float e0 = (gr0 == gc0) ? 0.f : __expf(INVT * c[mi][ni][0]);
                float e1 = (gr0 == gc1) ? 0.f : __expf(INVT * c[mi][ni][1]);
                float e2 = (gr1 == gc0) ? 0.f : __expf(INVT * c[mi][ni][2]);
                float e3 = (gr1 == gc1) ? 0.f : __expf(INVT * c[mi][ni][3]);
                acc[mi * 2 + 0] += e0 + e1;
                acc[mi * 2 + 1] += e2 + e3;
            }
        }
    }

    // reduce across the 4 lanes of each quad (same row, different cols)
    #pragma unroll
    for (int q = 0; q < 4; ++q) {
        acc[q] += __shfl_xor_sync(0xffffffffu, acc[q], 1);
        acc[q] += __shfl_xor_sync(0xffffffffu, acc[q], 2);
    }
    if (quad == 0) {
        int slot = blockIdx.y * 2 + warpN;   // 0..7, unique writer per row
        int r0 = rowBase + warpM * 32 + lrow;
        g_part[slot][r0]      = acc[0];
        g_part[slot][r0 + 8]  = acc[1];
        g_part[slot][r0 + 16] = acc[2];
        g_part[slot][r0 + 24] = acc[3];
    }
}

// ---------------------------------------------------------------------------
// Kernel 4: loss = mean over rows of log(sum partials) - pos
// ---------------------------------------------------------------------------
__global__ void loss_kernel(float* __restrict__ out) {
    __shared__ float red[1024];
    int t = threadIdx.x;
    float s = 0.f;
    for (int r = t; r < N2; r += 1024) {
        float rs = 0.f;
        #pragma unroll
        for (int p = 0; p < 8; ++p) rs += g_part[p][r];
        s += logf(rs) - g_pos[r];
    }
    red[t] = s;
    __syncthreads();
    for (int o = 512; o; o >>= 1) {
        if (t < o) red[t] += red[t + o];
        __syncthreads();
    }
    if (t == 0) out[0] = red[0] / (float)N2;
}

// ---------------------------------------------------------------------------
extern "C" void kernel_launch(void* const* d_in, const int* in_sizes, int n_in,
                              void* d_out, int out_size) {
    const float* zi = (const float*)d_in[0];
    const float* zj = (const float*)d_in[1];
    float* out = (float*)d_out;

    const int SMEM_BYTES = 2 * 128 * LDSU * 4;  // 135168
    cudaFuncSetAttribute(main_kernel, cudaFuncAttributeMaxDynamicSharedMemorySize,
                         SMEM_BYTES);

    prep_kernel<<<N2, 256>>>(zi, zj);
    pos_kernel<<<N2 / 8, 256>>>();
    main_kernel<<<dim3(64, 4), 256, SMEM_BYTES>>>();
    loss_kernel<<<1, 1024>>>(out);
}

// round 17
// speedup vs baseline: 1.0037x; 1.0009x over previous
#include <cuda_runtime.h>
#include <cuda_bf16.h>
#include <cstdint>

// NT-Xent: B=4096, D=256, T=0.1
#define N2   8192
#define BH   4096
#define D    256
#define INVT 10.0f

// Scratch (device globals — no allocation allowed)
__device__ __align__(256) __nv_bfloat16 g_pnh[N2 * D];   // normalized rows, bf16 (4 MB)
__device__ __align__(256) float         g_pnf[N2 * D];   // normalized rows, fp32 (8 MB)
__device__ float g_pos[N2];
__device__ float g_part[8][N2];                          // per-(colsplit,warpN) row partials

// ---------------------------------------------------------------------------
// Kernel 1: row-normalize (concat of z_i, z_j) -> fp32 + bf16 copies
// one block (256 threads) per row
// ---------------------------------------------------------------------------
__global__ void prep_kernel(const float* __restrict__ zi, const float* __restrict__ zj) {
    int row = blockIdx.x;
    int t   = threadIdx.x;
    const float* src = (row < BH) ? (zi + (size_t)row * D) : (zj + (size_t)(row - BH) * D);
    float v  = src[t];
    float ss = v * v;
    #pragma unroll
    for (int o = 16; o; o >>= 1) ss += __shfl_xor_sync(0xffffffffu, ss, o);

    __shared__ float wsum[8];
    __shared__ float inv_s;
    int wid = t >> 5, lane = t & 31;
    if (lane == 0) wsum[wid] = ss;
    __syncthreads();
    if (t == 0) {
        float tot = 0.f;
        #pragma unroll
        for (int i = 0; i < 8; ++i) tot += wsum[i];
        inv_s = 1.0f / fmaxf(sqrtf(tot), 1e-8f);
    }
    __syncthreads();
    float o = v * inv_s;
    g_pnf[(size_t)row * D + t] = o;
    g_pnh[(size_t)row * D + t] = __float2bfloat16(o);
}

// ---------------------------------------------------------------------------
// Kernel 2: exact fp32 positive-pair similarity. One warp per row.
// ---------------------------------------------------------------------------
__global__ void pos_kernel() {
    int gwarp = (blockIdx.x * blockDim.x + threadIdx.x) >> 5;
    int lane  = threadIdx.x & 31;
    int i = gwarp;
    int j = (i + BH) & (N2 - 1);
    const float* a = g_pnf + (size_t)i * D;
    const float* b = g_pnf + (size_t)j * D;
    float s = 0.f;
    #pragma unroll
    for (int k = 0; k < D; k += 32) s = fmaf(a[k + lane], b[k + lane], s);
    #pragma unroll
    for (int o = 16; o; o >>= 1) s += __shfl_xor_sync(0xffffffffu, s, o);
    if (lane == 0) g_pos[i] = s * INVT;
}

// ---------------------------------------------------------------------------
// Kernel 3: fused GEMM (pn @ pn^T) + diag-masked exp-sum per row.
// CTA tile 128 rows x 128 cols, K=256 fully resident. 8 warps: 4(M) x 2(N),
// warp tile 32x64, mma.sync.m16n8k16 bf16 -> fp32.
// grid = (64 row tiles, 4 column splits); deterministic partial writes.
// ---------------------------------------------------------------------------
#define LDSU 132   // u32 per SMEM row: 128 data + 4 pad (528 B, conflict-free)

__device__ __forceinline__ void mma16816(float c[4], const uint32_t a[4],
                                         uint32_t b0, uint32_t b1) {
    asm volatile(
        "mma.sync.aligned.m16n8k16.row.col.f32.bf16.bf16.f32 "
        "{%0,%1,%2,%3}, {%4,%5,%6,%7}, {%8,%9}, {%0,%1,%2,%3};\n"
        : "+f"(c[0]), "+f"(c[1]), "+f"(c[2]), "+f"(c[3])
        : "r"(a[0]), "r"(a[1]), "r"(a[2]), "r"(a[3]), "r"(b0), "r"(b1));
}

__global__ void __launch_bounds__(256, 1) main_kernel() {
    extern __shared__ uint32_t sm[];
    uint32_t* As = sm;                 // 128 x 132 u32
    uint32_t* Bs = sm + 128 * LDSU;    // 128 x 132 u32

    int tid  = threadIdx.x;
    int lane = tid & 31;
    int warp = tid >> 5;
    int warpM = warp & 3;              // 0..3  (rows)
    int warpN = warp >> 2;             // 0..1  (cols)
    int quad  = lane & 3;
    int lrow  = lane >> 2;
    int rowBase = blockIdx.x * 128;

    // ---- load A tile (128 x 256 bf16) ----
    {
        const uint4* src = (const uint4*)g_pnh;
        #pragma unroll
        for (int it = 0; it < 16; ++it) {
            int idx = tid + it * 256;          // 0..4095
            int row = idx >> 5, kv = idx & 31; // kv: uint4 (8 bf16) within row
            uint4 v = src[(size_t)(rowBase + row) * (D / 8) + kv];
            *(uint4*)&As[row * LDSU + kv * 4] = v;
        }
    }

    float acc[4] = {0.f, 0.f, 0.f, 0.f};

    const uint32_t* A0 = &As[(warpM * 32 + lrow) * LDSU];
    const uint32_t* B0 = &Bs[(warpN * 64 + lrow) * LDSU];

    for (int ct = 0; ct < 16; ++ct) {
        int colBase = blockIdx.y * 2048 + ct * 128;

        __syncthreads();   // prior consumers of Bs done (also orders A stores on ct=0)
        {
            const uint4* src = (const uint4*)g_pnh;
            #pragma unroll
            for (int it = 0; it < 16; ++it) {
                int idx = tid + it * 256;
                int row = idx >> 5, kv = idx & 31;
                uint4 v = src[(size_t)(colBase + row) * (D / 8) + kv];
                *(uint4*)&Bs[row * LDSU + kv * 4] = v;
            }
        }
        __syncthreads();

        float c[2][8][4];
        #pragma unroll
        for (int mi = 0; mi < 2; ++mi)
            #pragma unroll
            for (int ni = 0; ni < 8; ++ni)
                #pragma unroll
                for (int q = 0; q < 4; ++q) c[mi][ni][q] = 0.f;

        #pragma unroll
        for (int kc = 0; kc < 16; ++kc) {
            int ku = kc * 8 + quad;            // u32 index into a 128-u32 row
            uint32_t a[2][4];
            #pragma unroll
            for (int mi = 0; mi < 2; ++mi) {
                const uint32_t* p = A0 + mi * 16 * LDSU;
                a[mi][0] = p[ku];
                a[mi][1] = p[8 * LDSU + ku];
                a[mi][2] = p[ku + 4];
                a[mi][3] = p[8 * LDSU + ku + 4];
            }
            #pragma unroll
            for (int ni = 0; ni < 8; ++ni) {
                const uint32_t* p = B0 + ni * 8 * LDSU;
                uint32_t b0 = p[ku];
                uint32_t b1 = p[ku + 4];
                mma16816(c[0][ni], a[0], b0, b1);
                mma16816(c[1][ni], a[1], b0, b1);
            }
        }

        // ---- epilogue: exp + diag mask, accumulate per-row ----
        #pragma unroll
        for (int mi = 0; mi < 2; ++mi) {
            int gr0 = rowBase + warpM * 32 + mi * 16 + lrow;
            int gr1 = gr0 + 8;
            #pragma unroll
            for (int ni = 0; ni < 8; ++ni) {
                int gc0 = colBase + warpN * 64 + ni * 8 + quad * 2;
                int gc1 = gc0 + 1;
                float e0 = (gr0 == gc0) ? 0.f : __expf(INVT * c[mi][ni][0]);
                float e1 = (gr0 == gc1) ? 0.f : __expf(INVT * c[mi][ni][1]);
                float e2 = (gr1 == gc0) ? 0.f : __expf(INVT * c[mi][ni][2]);
                float e3 = (gr1 == gc1) ? 0.f : __expf(INVT * c[mi][ni][3]);
                acc[mi * 2 + 0] += e0 + e1;
                acc[mi * 2 + 1] += e2 + e3;
            }
        }
    }

    // reduce across the 4 lanes of each quad (same row, different cols)
    #pragma unroll
    for (int q = 0; q < 4; ++q) {
        acc[q] += __shfl_xor_sync(0xffffffffu, acc[q], 1);
        acc[q] += __shfl_xor_sync(0xffffffffu, acc[q], 2);
    }
    if (quad == 0) {
        int slot = blockIdx.y * 2 + warpN;   // 0..7, unique writer per row
        int r0 = rowBase + warpM * 32 + lrow;
        g_part[slot][r0]      = acc[0];
        g_part[slot][r0 + 8]  = acc[1];
        g_part[slot][r0 + 16] = acc[2];
        g_part[slot][r0 + 24] = acc[3];
    }
}

// ---------------------------------------------------------------------------
// Kernel 4: loss = mean over rows of log(sum partials) - pos
// ---------------------------------------------------------------------------
__global__ void loss_kernel(float* __restrict__ out) {
    __shared__ float red[1024];
    int t = threadIdx.x;
    float s = 0.f;
    for (int r = t; r < N2; r += 1024) {
        float rs = 0.f;
        #pragma unroll
        for (int p = 0; p < 8; ++p) rs += g_part[p][r];
        s += logf(rs) - g_pos[r];
    }
    red[t] = s;
    __syncthreads();
    for (int o = 512; o; o >>= 1) {
        if (t < o) red[t] += red[t + o];
        __syncthreads();
    }
    if (t == 0) out[0] = red[0] / (float)N2;
}

// ---------------------------------------------------------------------------
extern "C" void kernel_launch(void* const* d_in, const int* in_sizes, int n_in,
                              void* d_out, int out_size) {
    const float* zi = (const float*)d_in[0];
    const float* zj = (const float*)d_in[1];
    float* out = (float*)d_out;

    const int SMEM_BYTES = 2 * 128 * LDSU * 4;  // 135168
    cudaFuncSetAttribute(main_kernel, cudaFuncAttributeMaxDynamicSharedMemorySize,
                         SMEM_BYTES);

    prep_kernel<<<N2, 256>>>(zi, zj);
    pos_kernel<<<N2 / 8, 256>>>();
    main_kernel<<<dim3(64, 4), 256, SMEM_BYTES>>>();
    loss_kernel<<<1, 1024>>>(out);
}